// round 9
// baseline (speedup 1.0000x reference)
#include <cuda_runtime.h>
#include <math_constants.h>

#define NROWS 2048
#define DIM   1024
#define KCENT 256
#define NMID  272            // 256 + 16 pad (+inf)
#define NB    1024
#define TPB   256

__device__ float4 g_lut4[NB];      // (mid[i+3], mid[i+7], mid[i+11], bits(i))
__device__ float  g_smids[NMID];   // midpoints, [255..271] = +inf
__device__ float  g_scen[KCENT];   // centroids
__device__ float  g_sb[2];         // scale, bias
__device__ float  g_norm[NROWS];   // per-row norms

// -------- kernel A: LUT build (CTAs 0-3) + norms (CTAs 4-259) --------
__global__ __launch_bounds__(TPB)
void prep_norm_kernel(const float* __restrict__ x,
                      const float* __restrict__ centroids) {
    const int t = threadIdx.x;

    if (blockIdx.x < 4) {
        __shared__ float smidp[NMID];
        __shared__ int   sbin[KCENT];

        const float c0 = centroids[t];
        const float c1 = centroids[t < KCENT - 1 ? t + 1 : KCENT - 1];
        const float mid = (t < KCENT - 1) ? 0.5f * (c0 + c1) : CUDART_INF_F;
        smidp[t] = mid;
        if (t < NMID - KCENT) smidp[KCENT + t] = CUDART_INF_F;
        if (blockIdx.x == 0) {
            g_smids[t] = mid;
            if (t < NMID - KCENT) g_smids[KCENT + t] = CUDART_INF_F;
            g_scen[t] = c0;
        }
        __syncthreads();

        const float lo    = smidp[0];
        const float hi    = smidp[KCENT - 2];
        const float scale = (float)NB / fmaxf(hi - lo, 1e-30f);
        const float bias  = -lo * scale;
        if (blockIdx.x == 0 && t == 0) { g_sb[0] = scale; g_sb[1] = bias; }

        // bins of midpoints (sorted, bin() monotone); sentinel for t=255
        int mybin = 0x7fffffff;
        if (t < KCENT - 1) {
            float bf = fmaf(mid, scale, bias);
            mybin = (int)fminf(fmaxf(bf, 0.0f), (float)(NB - 1));
        }
        sbin[t] = mybin;
        __syncthreads();

        // pos = lower_bound(sbin, b) = #{m : bin(m) < b}  (8-step branchless)
        const int b = blockIdx.x * TPB + t;
        int pos = 0;
        #pragma unroll
        for (int s = 128; s; s >>= 1) {
            int np = pos + s;
            if (sbin[np - 1] < b) pos = np;
        }
        g_lut4[b] = make_float4(smidp[pos + 3], smidp[pos + 7], smidp[pos + 11],
                                __int_as_float(pos));
    } else {
        // norms: warp per row, 8 rows/CTA
        const int lane = t & 31;
        const int row  = (blockIdx.x - 4) * 8 + (t >> 5);
        const float4* __restrict__ xr =
            reinterpret_cast<const float4*>(x) + (size_t)row * (DIM / 4);

        float ss = 0.f;
        #pragma unroll
        for (int k = 0; k < 8; k++) {
            float4 v = xr[k * 32 + lane];
            ss += v.x * v.x + v.y * v.y + v.z * v.z + v.w * v.w;
        }
        #pragma unroll
        for (int o = 16; o; o >>= 1) ss += __shfl_xor_sync(0xffffffffu, ss, o);
        if (lane == 0) g_norm[row] = fmaxf(sqrtf(ss), 1e-8f);
    }
}

// -------- kernel B: 2 rows/CTA, depth-3 quantizer, one barrier --------
__global__ __launch_bounds__(TPB, 8)
void planar_quant_kernel(const float* __restrict__ x,
                         const float* __restrict__ rot2,
                         float* __restrict__ out_xhat,
                         float* __restrict__ out_idx,
                         int write_idx) {
    __shared__ float4 lut4[NB];        // 16 KB
    __shared__ float  smids[NMID];     // 1.1 KB
    __shared__ float  scen[KCENT];     // 1 KB

    const int t    = threadIdx.x;
    const int rowA = blockIdx.x * 2;
    const int rowB = rowA + 1;

    // ---- long-latency loads first ----
    const float4 xvA = reinterpret_cast<const float4*>(x + (size_t)rowA * DIM)[t];
    const float4 xvB = reinterpret_cast<const float4*>(x + (size_t)rowB * DIM)[t];
    const float4 rv  = reinterpret_cast<const float4*>(rot2)[t];
    const float normA = g_norm[rowA];
    const float normB = g_norm[rowB];
    const float scale = g_sb[0];
    const float bias  = g_sb[1];

    // ---- table copy: lut4 1024 f4 (4/thr), smids 68 f4, scen 64 f4 ----
    #pragma unroll
    for (int k = 0; k < 4; k++)
        lut4[t + k * TPB] = g_lut4[t + k * TPB];
    if (t < NMID / 4)
        reinterpret_cast<float4*>(smids)[t] = reinterpret_cast<const float4*>(g_smids)[t];
    if (t < KCENT / 4)
        reinterpret_cast<float4*>(scen)[t]  = reinterpret_cast<const float4*>(g_scen)[t];

    __syncthreads();   // single barrier: table visibility

    const float rnA = 1.0f / normA;
    const float rnB = 1.0f / normB;

    // depth-3 quant: LDS.128 (thresholds+base) -> 3 parallel LDS.32 -> payload
    auto quant = [&](float v, int& idx, float& q) {
        float bf = fmaf(v, scale, bias);
        int b = (int)fminf(fmaxf(bf, 0.0f), (float)(NB - 1));
        float4 f = lut4[b];
        int i = __float_as_int(f.w);
        int s = (f.x < v) + (f.y < v) + (f.z < v);     // o>=4, o>=8, o>=12
        i += 4 * s;
        i += (smids[i] < v) + (smids[i + 1] < v) + (smids[i + 2] < v);
        idx = i;
        q = scen[i];
    };

    #pragma unroll
    for (int r = 0; r < 2; r++) {
        const float4 xv  = r ? xvB : xvA;
        const float  rn  = r ? rnB : rnA;
        const float  nrm = r ? normB : normA;
        const int    row = r ? rowB : rowA;

        const float v0 = xv.x * rn, v1 = xv.y * rn;
        const float v2 = xv.z * rn, v3 = xv.w * rn;
        const float r0 = rv.x * v0 - rv.y * v1;
        const float r1 = rv.y * v0 + rv.x * v1;
        const float r2 = rv.z * v2 - rv.w * v3;
        const float r3 = rv.w * v2 + rv.z * v3;

        int   i0, i1, i2, i3;
        float q0, q1, q2, q3;
        quant(r0, i0, q0);
        quant(r1, i1, q1);
        quant(r2, i2, q2);
        quant(r3, i3, q3);

        float4 xh;
        xh.x = ( rv.x * q0 + rv.y * q1) * nrm;
        xh.y = (-rv.y * q0 + rv.x * q1) * nrm;
        xh.z = ( rv.z * q2 + rv.w * q3) * nrm;
        xh.w = (-rv.w * q2 + rv.z * q3) * nrm;
        reinterpret_cast<float4*>(out_xhat + (size_t)row * DIM)[t] = xh;

        if (write_idx) {
            float4 fi;
            fi.x = (float)i0; fi.y = (float)i1; fi.z = (float)i2; fi.w = (float)i3;
            reinterpret_cast<float4*>(out_idx + (size_t)row * DIM)[t] = fi;
        }
    }
}

extern "C" void kernel_launch(void* const* d_in, const int* in_sizes, int n_in,
                              void* d_out, int out_size) {
    const float* x         = (const float*)d_in[0];  // [2048, 1024]
    const float* centroids = (const float*)d_in[1];  // [256]
    const float* rot2      = (const float*)d_in[2];  // [512, 2]

    float* out = (float*)d_out;
    const int full = (out_size >= 2 * NROWS * DIM);
    float* out_xhat = out;
    float* out_idx  = full ? out + (size_t)NROWS * DIM : out;

    prep_norm_kernel<<<4 + NROWS / 8, TPB>>>(x, centroids);
    planar_quant_kernel<<<NROWS / 2, TPB>>>(x, rot2, out_xhat, out_idx, full);
}

// round 10
// speedup vs baseline: 1.0625x; 1.0625x over previous
#include <cuda_runtime.h>
#include <math_constants.h>

#define NROWS 2048
#define DIM   1024
#define KCENT 256
#define NMID  272            // 256 + 16 pad (+inf)
#define NB    1024
#define TPB   256

__device__ int   g_luti[NB];      // per-bin lower-bound index
__device__ float g_smids[NMID];   // midpoints, [255..271] = +inf
__device__ float g_scen[KCENT];   // centroids
__device__ float g_sb[2];         // scale, bias

// -------- prep: 4 CTAs build the LUT (no atomics, no scan) --------
__global__ __launch_bounds__(TPB)
void prep_kernel(const float* __restrict__ centroids) {
    __shared__ float smidp[KCENT];
    __shared__ int   sbin[KCENT];

    const int t = threadIdx.x;

    const float c0 = centroids[t];
    const float c1 = centroids[t < KCENT - 1 ? t + 1 : KCENT - 1];
    const float mid = (t < KCENT - 1) ? 0.5f * (c0 + c1) : CUDART_INF_F;
    smidp[t] = mid;
    if (blockIdx.x == 0) {
        g_smids[t] = mid;
        if (t < NMID - KCENT) g_smids[KCENT + t] = CUDART_INF_F;
        g_scen[t] = c0;
    }
    __syncthreads();

    const float lo    = smidp[0];
    const float hi    = smidp[KCENT - 2];
    const float scale = (float)NB / fmaxf(hi - lo, 1e-30f);
    const float bias  = -lo * scale;
    if (blockIdx.x == 0 && t == 0) { g_sb[0] = scale; g_sb[1] = bias; }

    // bins of midpoints (sorted since bin() is monotone); sentinel at t=255
    int mybin = 0x7fffffff;
    if (t < KCENT - 1) {
        float bf = fmaf(mid, scale, bias);
        mybin = (int)fminf(fmaxf(bf, 0.0f), (float)(NB - 1));
    }
    sbin[t] = mybin;
    __syncthreads();

    // luti[b] = #{m : bin(m) < b} via 8-step branchless lower bound
    const int b = blockIdx.x * TPB + t;
    int pos = 0;
    #pragma unroll
    for (int s = 128; s; s >>= 1) {
        int np = pos + s;
        if (sbin[np - 1] < b) pos = np;
    }
    g_luti[b] = pos;
}

// -------- main: 2 rows/CTA, single wave, fused norms, one barrier --------
__global__ __launch_bounds__(TPB, 8)
void planar_quant_kernel(const float* __restrict__ x,
                         const float* __restrict__ rot2,
                         float* __restrict__ out_xhat,
                         float* __restrict__ out_idx,
                         int write_idx) {
    __shared__ int   luti[NB];       // 4 KB
    __shared__ float smids[NMID];
    __shared__ float scen[KCENT];
    __shared__ float sred[2][8];

    const int t    = threadIdx.x;
    const int lane = t & 31;
    const int wid  = t >> 5;
    const int rowA = blockIdx.x * 2;
    const int rowB = rowA + 1;

    // ---- long-latency loads first ----
    const float4 xvA = reinterpret_cast<const float4*>(x + (size_t)rowA * DIM)[t];
    const float4 xvB = reinterpret_cast<const float4*>(x + (size_t)rowB * DIM)[t];
    const float4 rv  = reinterpret_cast<const float4*>(rot2)[t];
    const float scale = g_sb[0];
    const float bias  = g_sb[1];

    // ---- table copy (coalesced vector loads) ----
    reinterpret_cast<int4*>(luti)[t] = reinterpret_cast<const int4*>(g_luti)[t];
    if (t < NMID / 4)
        reinterpret_cast<float4*>(smids)[t] = reinterpret_cast<const float4*>(g_smids)[t];
    if (t < KCENT / 4)
        reinterpret_cast<float4*>(scen)[t]  = reinterpret_cast<const float4*>(g_scen)[t];

    // ---- norm partials for both rows (shuffle-only) ----
    float ssA = xvA.x * xvA.x + xvA.y * xvA.y + xvA.z * xvA.z + xvA.w * xvA.w;
    float ssB = xvB.x * xvB.x + xvB.y * xvB.y + xvB.z * xvB.z + xvB.w * xvB.w;
    #pragma unroll
    for (int o = 16; o; o >>= 1) {
        ssA += __shfl_xor_sync(0xffffffffu, ssA, o);
        ssB += __shfl_xor_sync(0xffffffffu, ssB, o);
    }
    if (lane == 0) { sred[0][wid] = ssA; sred[1][wid] = ssB; }

    __syncthreads();   // single barrier: tables + partials

    float4 a0 = reinterpret_cast<float4*>(sred[0])[0];
    float4 a1 = reinterpret_cast<float4*>(sred[0])[1];
    float4 b0 = reinterpret_cast<float4*>(sred[1])[0];
    float4 b1 = reinterpret_cast<float4*>(sred[1])[1];
    const float normA = fmaxf(sqrtf((a0.x + a0.y) + (a0.z + a0.w) +
                                    (a1.x + a1.y) + (a1.z + a1.w)), 1e-8f);
    const float normB = fmaxf(sqrtf((b0.x + b0.y) + (b0.z + b0.w) +
                                    (b1.x + b1.y) + (b1.z + b1.w)), 1e-8f);
    const float rnA = 1.0f / normA;
    const float rnB = 1.0f / normB;

    // branchless quant, all LDS.32: luti -> probes {8,4,2,1} -> payload
    auto quant = [&](float v, int& idx, float& q) {
        float bf = fmaf(v, scale, bias);
        int b = (int)fminf(fmaxf(bf, 0.0f), (float)(NB - 1));
        int i = luti[b];
        i += (smids[i + 7] < v) ? 8 : 0;
        i += (smids[i + 3] < v) ? 4 : 0;
        i += (smids[i + 1] < v) ? 2 : 0;
        i += (smids[i]     < v) ? 1 : 0;
        idx = i;
        q = scen[i];
    };

    #pragma unroll
    for (int r = 0; r < 2; r++) {
        const float4 xv  = r ? xvB : xvA;
        const float  rn  = r ? rnB : rnA;
        const float  nrm = r ? normB : normA;
        const int    row = r ? rowB : rowA;

        const float v0 = xv.x * rn, v1 = xv.y * rn;
        const float v2 = xv.z * rn, v3 = xv.w * rn;
        const float r0 = rv.x * v0 - rv.y * v1;
        const float r1 = rv.y * v0 + rv.x * v1;
        const float r2 = rv.z * v2 - rv.w * v3;
        const float r3 = rv.w * v2 + rv.z * v3;

        int   i0, i1, i2, i3;
        float q0, q1, q2, q3;
        quant(r0, i0, q0);
        quant(r1, i1, q1);
        quant(r2, i2, q2);
        quant(r3, i3, q3);

        float4 xh;
        xh.x = ( rv.x * q0 + rv.y * q1) * nrm;
        xh.y = (-rv.y * q0 + rv.x * q1) * nrm;
        xh.z = ( rv.z * q2 + rv.w * q3) * nrm;
        xh.w = (-rv.w * q2 + rv.z * q3) * nrm;
        reinterpret_cast<float4*>(out_xhat + (size_t)row * DIM)[t] = xh;

        if (write_idx) {
            float4 fi;
            fi.x = (float)i0; fi.y = (float)i1; fi.z = (float)i2; fi.w = (float)i3;
            reinterpret_cast<float4*>(out_idx + (size_t)row * DIM)[t] = fi;
        }
    }
}

extern "C" void kernel_launch(void* const* d_in, const int* in_sizes, int n_in,
                              void* d_out, int out_size) {
    const float* x         = (const float*)d_in[0];  // [2048, 1024]
    const float* centroids = (const float*)d_in[1];  // [256]
    const float* rot2      = (const float*)d_in[2];  // [512, 2]

    float* out = (float*)d_out;
    const int full = (out_size >= 2 * NROWS * DIM);
    float* out_xhat = out;
    float* out_idx  = full ? out + (size_t)NROWS * DIM : out;

    prep_kernel<<<4, TPB>>>(centroids);
    planar_quant_kernel<<<NROWS / 2, TPB>>>(x, rot2, out_xhat, out_idx, full);
}